// round 11
// baseline (speedup 1.0000x reference)
#include <cuda_runtime.h>
#include <cstdint>

// Problem constants
#define Bsz 32
#define Lsz 4096
#define Isz 128
#define Hsz 256
#define Osz 128
#define NDELAY 5      // delay line length (DELAY+1)

// Scratch (static device globals: allocation-free per harness rules)
__device__ float g_xz[Bsz * Lsz * Hsz];
__device__ float g_xh[Bsz * Lsz * Hsz];
__device__ float g_hs[Bsz * Lsz * Hsz];

// ---------------------------------------------------------------------------
// fp32 tiled GEMM with bias, packed f32x2 accumulation.
// C[M,N] = A[M,K] @ B[K,N] + bias[N]; 64x64 tile, 256 threads, 4x4 micro.
// ---------------------------------------------------------------------------
__global__ void __launch_bounds__(256) gemm_bias(
    const float* __restrict__ A, const float* __restrict__ Bm,
    const float* __restrict__ bias, float* __restrict__ C,
    int M, int K, int N)
{
    __shared__ float sA[64][68];
    __shared__ float sB[64][68];

    const int m0  = blockIdx.x << 6;
    const int n0  = blockIdx.y << 6;
    const int tid = threadIdx.x;
    const int tx  = tid & 15;
    const int ty  = tid >> 4;

    uint64_t acc01[4], acc23[4];   // packed (col0,col1) / (col2,col3) per row
#pragma unroll
    for (int i = 0; i < 4; i++) { acc01[i] = 0; acc23[i] = 0; }

    for (int kk = 0; kk < K; kk += 64) {
#pragma unroll
        for (int i = 0; i < 4; i++) {
            int lin = tid + (i << 8);
            int r   = lin >> 4;
            int c   = (lin & 15) << 2;
            *(float4*)&sA[r][c] = *(const float4*)&A[(size_t)(m0 + r) * K + kk + c];
            *(float4*)&sB[r][c] = *(const float4*)&Bm[(size_t)(kk + r) * N + n0 + c];
        }
        __syncthreads();

#pragma unroll 16
        for (int k = 0; k < 64; k++) {
            ulonglong2 bb = *(const ulonglong2*)&sB[k][tx << 2];
#pragma unroll
            for (int i = 0; i < 4; i++) {
                float a = sA[(ty << 2) + i][k];
                uint64_t aa;
                asm("mov.b64 %0, {%1, %1};" : "=l"(aa) : "f"(a));
                asm("fma.rn.f32x2 %0, %1, %2, %0;" : "+l"(acc01[i]) : "l"(aa), "l"(bb.x));
                asm("fma.rn.f32x2 %0, %1, %2, %0;" : "+l"(acc23[i]) : "l"(aa), "l"(bb.y));
            }
        }
        __syncthreads();
    }

    float4 bb = *(const float4*)&bias[n0 + (tx << 2)];
#pragma unroll
    for (int i = 0; i < 4; i++) {
        float c0, c1, c2, c3;
        asm("mov.b64 {%0, %1}, %2;" : "=f"(c0), "=f"(c1) : "l"(acc01[i]));
        asm("mov.b64 {%0, %1}, %2;" : "=f"(c2), "=f"(c3) : "l"(acc23[i]));
        float4 o;
        o.x = c0 + bb.x; o.y = c1 + bb.y; o.z = c2 + bb.z; o.w = c3 + bb.w;
        *(float4*)&C[(size_t)(m0 + (ty << 2) + i) * N + n0 + (tx << 2)] = o;
    }
}

// ---------------------------------------------------------------------------
// Fast-math helpers (ex2/rcp approx: rel err ~1e-7)
// ---------------------------------------------------------------------------
__device__ __forceinline__ float ex2_fast(float x) {
    float r; asm("ex2.approx.f32 %0, %1;" : "=f"(r) : "f"(x)); return r;
}
__device__ __forceinline__ float rcp_fast(float x) {
    float r; asm("rcp.approx.f32 %0, %1;" : "=f"(r) : "f"(x)); return r;
}
__device__ __forceinline__ float sigmoid_fast(float x) {
    return rcp_fast(1.f + ex2_fast(-1.4426950408889634f * x));
}
__device__ __forceinline__ float tanh_fast(float x) {
    float e = ex2_fast(2.885390081777927f * x);
    return (e - 1.f) * rcp_fast(e + 1.f);
}

// Packed f32x2 dot over 64 floats; all lanes read the SAME addresses
// (whole-warp broadcast -> conflict-free, 1 wavefront per LDS.128).
__device__ __forceinline__ float dot64_bcast(const float* p, const uint64_t* w) {
    const ulonglong2* v = (const ulonglong2*)p;
    uint64_t a0 = 0, a1 = 0, a2 = 0, a3 = 0;
#pragma unroll
    for (int j = 0; j < 8; j++) {
        ulonglong2 t = v[j];
        asm("fma.rn.f32x2 %0, %1, %2, %0;" : "+l"(a0) : "l"(t.x), "l"(w[2*j]));
        asm("fma.rn.f32x2 %0, %1, %2, %0;" : "+l"(a1) : "l"(t.y), "l"(w[2*j+1]));
    }
#pragma unroll
    for (int j = 8; j < 16; j++) {
        ulonglong2 t = v[j];
        asm("fma.rn.f32x2 %0, %1, %2, %0;" : "+l"(a2) : "l"(t.x), "l"(w[2*j]));
        asm("fma.rn.f32x2 %0, %1, %2, %0;" : "+l"(a3) : "l"(t.y), "l"(w[2*j+1]));
    }
    uint64_t s01, s23, s;
    asm("add.rn.f32x2 %0, %1, %2;" : "=l"(s01) : "l"(a0), "l"(a1));
    asm("add.rn.f32x2 %0, %1, %2;" : "=l"(s23) : "l"(a2), "l"(a3));
    asm("add.rn.f32x2 %0, %1, %2;" : "=l"(s)   : "l"(s01), "l"(s23));
    float lo, hi;
    asm("mov.b64 {%0, %1}, %2;" : "=f"(lo), "=f"(hi) : "l"(s));
    return lo + hi;
}

__device__ __forceinline__ uint64_t pack2(float lo, float hi) {
    uint64_t r; asm("mov.b64 %0, {%1, %2};" : "=l"(r) : "f"(lo), "f"(hi)); return r;
}

__device__ __forceinline__ void mbar_expect_tx(uint32_t mbar, uint32_t bytes) {
    asm volatile("mbarrier.arrive.expect_tx.shared.b64 _, [%0], %1;"
                 :: "r"(mbar), "r"(bytes) : "memory");
}

__device__ __forceinline__ void mbar_wait(uint32_t mbar, uint32_t parity) {
    asm volatile(
        "{\n\t"
        ".reg .pred P;\n\t"
        "WAIT_%=:\n\t"
        "mbarrier.try_wait.parity.acquire.cluster.shared::cta.b64 P, [%0], %1, 10000000;\n\t"
        "@!P bra WAIT_%=;\n\t"
        "}"
        :: "r"(mbar), "r"(parity) : "memory");
}

// DSMEM bulk copy: local smem -> peer smem, complete_tx to peer's mbarrier.
__device__ __forceinline__ void bulk_s2s(uint32_t dst, uint32_t src,
                                         uint32_t bytes, uint32_t mbar) {
    asm volatile(
        "cp.async.bulk.shared::cluster.shared::cta.mbarrier::complete_tx::bytes "
        "[%0], [%1], %2, [%3];"
        :: "r"(dst), "r"(src), "r"(bytes), "r"(mbar) : "memory");
}

__device__ __forceinline__ void fence_async() {
    asm volatile("fence.proxy.async.shared::cta;" ::: "memory");
}

// ---------------------------------------------------------------------------
// Sequential MGRU scan — partial-dot exchange, pipelined Uz partial,
// per-pair named barriers before the push.
//
// 32 clusters x 4 CTAs, one cluster per batch row. CTA r owns state indices
// G = [64r, 64r+64) both as hidden columns and as k-rows of Uz/Uh. Thread
// tid computes for global column jp=tid the k-partial over G:
//   pUh(t)   = sum_{k in G} a_k(t)   Uh[k,jp],  a(t)=z(t)(.)h(t-1) LOCAL
//   pUz(t+1) = sum_{k in G} h_k(t-3) Uz[k,jp]   (computed in step t's shadow,
//              staged at step t+1; z(s) uses h(s-5) => packet s carries
//              pUz from ring slot (s+1)%5)
// Packet t (per destination CTA: 64 pUh + 64 pUz floats, 512B) is pushed by
// warp-pair d (warps 2d,2d+1 produce slice d) right after bar.sync(d+1,64).
// Each CTA's mb[t&1] expects 2048 tx-bytes.
//
// Buffer-reuse safety (chains via mbarrier waits + end-of-step __syncthreads):
//   a_loc[p]     read at t, rewritten at t+2 after wait(t+1).
//   out_stage[p] bulk-source read at t completes before peer wait(t);
//                rewrite at t+2 follows our wait(t+1) <- peer push(t+1)
//                <- peer end-sync(t) <- peer wait(t).
//   inbox[p]     read by owners at t; peer rewrite at t+2 follows peer
//                wait(t+1) <- our push(t+1) <- our end-sync(t) <- reads.
//   hd_ring      slot s%5 written at update(s), read at shadow(s+3); the
//                shadow read at t of slot (t+2)%5 never collides with the
//                concurrent update(t) write of slot t%5.
// ---------------------------------------------------------------------------
__global__ void __launch_bounds__(256, 1) __cluster_dims__(4, 1, 1)
mgru_scan(const float* __restrict__ xz, const float* __restrict__ xh,
          const float* __restrict__ Uz, const float* __restrict__ Uh,
          float* __restrict__ hs)
{
    __shared__ __align__(16) float a_loc[2][64];        // a(t) local chunk
    __shared__ __align__(16) float hd_ring[NDELAY][64]; // local h history
    __shared__ __align__(16) float out_stage[2][512];   // [dst4][pUh64|pUz64]
    __shared__ __align__(16) float inbox[2][512];       // [src4][pUh64|pUz64]
    __shared__ __align__(8) unsigned long long mb[2];

    const int rank = blockIdx.x & 3;
    const int b    = blockIdx.x >> 2;
    const int tid  = threadIdx.x;
    const int lane = tid & 31;
    const int jp   = tid;                 // partial column (global, 0..255)
    const int pr   = tid >> 6;            // warp-pair index == destination CTA
    const int idx  = tid & 63;            // index within pair slice

    // Register-resident weight slices: rows k in G, column jp.
    uint64_t wz2[32], wh2[32];
    {
        const float* uz = Uz + (size_t)(rank * 64) * Hsz + jp;
        const float* uh = Uh + (size_t)(rank * 64) * Hsz + jp;
#pragma unroll
        for (int i = 0; i < 32; i++) {
            wz2[i] = pack2(uz[(size_t)(2*i) * Hsz], uz[(size_t)(2*i+1) * Hsz]);
            wh2[i] = pack2(uh[(size_t)(2*i) * Hsz], uh[(size_t)(2*i+1) * Hsz]);
        }
    }

    if (tid == 0) {
        uint32_t m0 = (uint32_t)__cvta_generic_to_shared(&mb[0]);
        asm volatile("mbarrier.init.shared.b64 [%0], 1;" :: "r"(m0) : "memory");
        asm volatile("mbarrier.init.shared.b64 [%0], 1;" :: "r"(m0 + 8) : "memory");
    }
    for (int i = tid; i < 2 * 64;      i += 256) (&a_loc[0][0])[i]     = 0.f;
    for (int i = tid; i < NDELAY * 64; i += 256) (&hd_ring[0][0])[i]   = 0.f;
    for (int i = tid; i < 2 * 512;     i += 256) (&out_stage[0][0])[i] = 0.f;
    for (int i = tid; i < 2 * 512;     i += 256) (&inbox[0][0])[i]     = 0.f;
    __syncthreads();
    // all CTAs' mbarriers + zeroed buffers visible before any async traffic
    asm volatile("barrier.cluster.arrive.aligned;" ::: "memory");
    asm volatile("barrier.cluster.wait.aligned;" ::: "memory");

    const uint32_t stage_sa = (uint32_t)__cvta_generic_to_shared(&out_stage[0][0]);
    const uint32_t inbox_sa = (uint32_t)__cvta_generic_to_shared(&inbox[0][0]);
    const uint32_t mb_sa    = (uint32_t)__cvta_generic_to_shared(&mb[0]);
    uint32_t peer_inbox = 0, peer_mb = 0;   // in CTA `pr`'s SMEM
    asm("mapa.shared::cluster.u32 %0, %1, %2;" : "=r"(peer_inbox) : "r"(inbox_sa), "r"(pr));
    asm("mapa.shared::cluster.u32 %0, %1, %2;" : "=r"(peer_mb)    : "r"(mb_sa),    "r"(pr));

    // Column-owner state (threads 0..63): jglob = 64*rank + tid
    const int jglob = rank * 64 + tid;    // valid for tid < 64
    const float* xzp = xz + (size_t)b * Lsz * Hsz + jglob;
    const float* xhp = xh + (size_t)b * Lsz * Hsz + jglob;
    float*       hsp = hs + (size_t)b * Lsz * Hsz + jglob;

    float h = 0.f, z = 0.f;
    float xh_cur = 0.f, xz_nxt = 0.f, xh_nxt = 0.f;
    if (tid < 64) {
        xh_cur = xhp[0];
        xz_nxt = xzp[Hsz];
        xh_nxt = xhp[Hsz];
        z      = sigmoid_fast(xzp[0]);   // z(0): h(-5) = 0
        // a(0) = z(0)*h(-1) = 0 -> a_loc[0] already zeroed
    }

    float pUz_next = 0.f;   // pUz for packet 0 (z(1) uses h(-4)=0)

    int slot_s = 2;  // (t+2)%5 : shadow-read h(t-3) for packet t+1
    int slot_w = 0;  // t%5     : write h(t)

    for (int t = 0; t < Lsz; ++t) {
        const int p = t & 1;
        const uint32_t boff = (uint32_t)(p << 3);
        const uint32_t pb   = (uint32_t)(p << 11);   // p*512 floats in bytes

        // ---- Uh partial from the local a(t) chunk (critical path)
        float pUh = dot64_bcast(&a_loc[p][0], wh2);
        out_stage[p][pr * 128 + idx]      = pUh;
        out_stage[p][pr * 128 + 64 + idx] = pUz_next;   // precomputed last step

        // pair barrier: warps 2*pr, 2*pr+1 produced slice pr -> push it
        asm volatile("bar.sync %0, 64;" :: "r"(pr + 1) : "memory");
        if (idx == 0) {
            fence_async();
            bulk_s2s(peer_inbox + pb + (uint32_t)(rank << 9),
                     stage_sa + pb + (uint32_t)(pr << 9),
                     512u, peer_mb + boff);
        }
        if (tid == 0) mbar_expect_tx(mb_sa + boff, 2048u);

        // ---- shadow work: pUz for packet t+1 (h(t-3)), gmem prefetch
        float pUz_sh = dot64_bcast(&hd_ring[slot_s][0], wz2);
        float xz_p2 = 0.f, xh_p2 = 0.f;
        if (tid < 64 && t + 2 < Lsz) {
            xz_p2 = __ldg(xzp + (size_t)(t + 2) * Hsz);
            xh_p2 = __ldg(xhp + (size_t)(t + 2) * Hsz);
        }

        // ---- only column-owner warps wait; others run to the end sync
        if (tid < 64) {
            if (lane == 0) mbar_wait(mb_sa + boff, (uint32_t)((t >> 1) & 1));
            __syncwarp();

            const float* ib = &inbox[p][0];
            float sh = (ib[tid]       + ib[128 + tid])
                     + (ib[256 + tid] + ib[384 + tid]);
            float sz = (ib[64 + tid]  + ib[192 + tid])
                     + (ib[320 + tid] + ib[448 + tid]);
            float ht = tanh_fast(sh + xh_cur);
            h = h + z * (ht - h);                  // h(t)
            float zn = sigmoid_fast(sz + xz_nxt);  // z(t+1)

            a_loc[p ^ 1][tid]    = zn * h;         // a(t+1) local chunk
            hd_ring[slot_w][tid] = h;              // h(t) into ring
            hsp[(size_t)t * Hsz] = h;

            z = zn;
            xh_cur = xh_nxt;
            xz_nxt = xz_p2;
            xh_nxt = xh_p2;
        }
        __syncthreads();

        pUz_next = pUz_sh;
        slot_s = (slot_s == NDELAY - 1) ? 0 : slot_s + 1;
        slot_w = (slot_w == NDELAY - 1) ? 0 : slot_w + 1;
    }

    // no CTA may exit while peer traffic targeting it may be in flight
    asm volatile("barrier.cluster.arrive.aligned;" ::: "memory");
    asm volatile("barrier.cluster.wait.aligned;" ::: "memory");
}

// Dummy so ncu (6th global launch; 2 harness launches precede ours) captures
// the scan.
__global__ void dummy_k() {}

// ---------------------------------------------------------------------------
// Launch: proj GEMMs -> dummy -> scan -> head GEMM
// ---------------------------------------------------------------------------
extern "C" void kernel_launch(void* const* d_in, const int* in_sizes, int n_in,
                              void* d_out, int out_size)
{
    const float* x  = (const float*)d_in[0];
    const float* Wz = (const float*)d_in[1];
    const float* Uz = (const float*)d_in[2];
    const float* bz = (const float*)d_in[3];
    const float* Wh = (const float*)d_in[4];
    const float* Uh = (const float*)d_in[5];
    const float* bh = (const float*)d_in[6];
    const float* Wo = (const float*)d_in[7];
    const float* bo = (const float*)d_in[8];
    float* y = (float*)d_out;

    float *xz_p = nullptr, *xh_p = nullptr, *hs_p = nullptr;
    cudaGetSymbolAddress((void**)&xz_p, g_xz);
    cudaGetSymbolAddress((void**)&xh_p, g_xh);
    cudaGetSymbolAddress((void**)&hs_p, g_hs);

    const int M = Bsz * Lsz;           // 131072
    dim3 blk(256);

    gemm_bias<<<dim3(M / 64, Hsz / 64), blk>>>(x, Wz, bz, xz_p, M, Isz, Hsz);
    gemm_bias<<<dim3(M / 64, Hsz / 64), blk>>>(x, Wh, bh, xh_p, M, Isz, Hsz);

    dummy_k<<<1, 1>>>();

    mgru_scan<<<Bsz * 4, 256>>>(xz_p, xh_p, Uz, Uh, hs_p);

    gemm_bias<<<dim3(M / 64, Osz / 64), blk>>>(hs_p, Wo, bo, y, M, Hsz, Osz);
}